// round 3
// baseline (speedup 1.0000x reference)
#include <cuda_runtime.h>
#include <cstdint>

#define THREADS 128
#define R 4               // rows per thread
#define KDIM 120
#define INP 512
#define NPAIR 13          // 13 f32x2 pairs = 26 cols (25 real + 1 zero pad)
#define WROW 28           // W row padded to 28 floats (112B, 16B-aligned)
#define KC 24             // k-chunk
#define NCHUNK 5
#define NJ2 (KC / 2)      // 12 k-pair slots per chunk
#define A_STRIDE 516      // floats per j2 plane row (512 data + 4 pad, bank-shifts per j2)

#define SW_FLOATS (KDIM * WROW)                 // 3360
#define U_OFF SW_FLOATS
#define PLANE_FLOATS (NJ2 * A_STRIDE)           // 6192
#define SX_FLOATS (2 * PLANE_FLOATS)            // 12384
#define SCR_STRIDE 27
#define RED_OFF (U_OFF + THREADS * SCR_STRIDE)  // 3360 + 3456
#define RAW_OFF (RED_OFF + 4 * 26)
#define OUT_OFF (RAW_OFF + 32)
#define SMEM_FLOATS (U_OFF + SX_FLOATS)         // 15744
#define SMEM_BYTES (SMEM_FLOATS * 4)            // 62976

typedef unsigned long long ull;

__device__ __forceinline__ ull dup2(float v) {
    ull r;
    asm("mov.b64 %0, {%1, %1};" : "=l"(r) : "r"(__float_as_uint(v)));
    return r;
}
__device__ __forceinline__ void ffma2(ull& d, ull a, ull b) {
    asm("fma.rn.f32x2 %0, %1, %2, %0;" : "+l"(d) : "l"(a), "l"(b));
}
__device__ __forceinline__ void unpack2(ull v, float& lo, float& hi) {
    unsigned int a, b2;
    asm("mov.b64 {%0, %1}, %2;" : "=r"(a), "=r"(b2) : "l"(v));
    lo = __uint_as_float(a);
    hi = __uint_as_float(b2);
}

extern __shared__ float smem[];

__global__ void __launch_bounds__(THREADS, 3)
caps_kernel(const float* __restrict__ x, const float* __restrict__ W, float* __restrict__ out)
{
    const int b = blockIdx.x;
    const int t = threadIdx.x;

    float* sW      = smem;                      // [120][28]
    float* sXA     = smem + U_OFF;              // plane A: rowpairs (4i,4i+1)
    float* sXB     = smem + U_OFF + PLANE_FLOATS; // plane B: rowpairs (4i+2,4i+3)
    float* scratch = smem + U_OFF;              // routing partials (aliases sX)
    float* red     = smem + RED_OFF;            // [4][26]
    float* raw     = smem + RAW_OFF;            // [25]
    float* sOut    = smem + OUT_OFF;            // [25]

    // ---- stage W: row-padded pairs, col 25 zeroed ----
    for (int idx = t; idx < KDIM * NPAIR; idx += THREADS) {
        int j = idx / NPAIR, p = idx % NPAIR;
        int c0 = 2 * p;
        sW[j * WROW + c0]     = W[j * 25 + c0];
        sW[j * WROW + c0 + 1] = (c0 + 1 < 25) ? W[j * 25 + c0 + 1] : 0.f;
    }

    // ---- GEMM: u_hat[4 rows][26 cols] in 52 f32x2 accumulators ----
    ull acc[R][NPAIR];
    #pragma unroll
    for (int r = 0; r < R; r++)
        #pragma unroll
        for (int p = 0; p < NPAIR; p++) acc[r][p] = 0ull;

    const float4* xg = reinterpret_cast<const float4*>(x) + (size_t)b * (INP * KDIM / 4);

    for (int kc = 0; kc < NCHUNK; kc++) {
        __syncthreads();                 // sX safe to overwrite (first pass: sW visible too)
        const int k0q = kc * (KC / 4);
        #pragma unroll
        for (int it2 = 0; it2 < (INP * (KC / 4)) / THREADS; it2++) {   // 24 float4/thread
            int idx  = t + it2 * THREADS;
            int row  = idx / (KC / 4);
            int slot = idx % (KC / 4);
            float4 v = xg[row * (KDIM / 4) + k0q + slot];
            // plane by (row mod 4): {0,1}->A, {2,3}->B; pair index = row/4; parity = row&1
            float* plane = ((row >> 1) & 1) ? sXB : sXA;
            float* p0 = plane + (2 * slot) * A_STRIDE + (row >> 2) * 4 + (row & 1) * 2;
            *reinterpret_cast<float2*>(p0)            = make_float2(v.x, v.y);  // j2 = 2*slot
            *reinterpret_cast<float2*>(p0 + A_STRIDE) = make_float2(v.z, v.w);  // j2 = 2*slot+1
        }
        __syncthreads();

        #pragma unroll 2
        for (int j2 = 0; j2 < NJ2; j2++) {
            // xa: {x(k0,4t), x(k1,4t), x(k0,4t+1), x(k1,4t+1)}; xb: rows 4t+2,4t+3
            float4 xa = *reinterpret_cast<const float4*>(sXA + j2 * A_STRIDE + t * 4);
            float4 xb = *reinterpret_cast<const float4*>(sXB + j2 * A_STRIDE + t * 4);
            ull f0[R] = { dup2(xa.x), dup2(xa.z), dup2(xb.x), dup2(xb.z) };  // k0
            ull f1[R] = { dup2(xa.y), dup2(xa.w), dup2(xb.y), dup2(xb.w) };  // k1

            const float* wr = sW + (kc * KC + 2 * j2) * WROW;
            // k0
            #pragma unroll
            for (int m = 0; m < 6; m++) {
                ulonglong2 w = *reinterpret_cast<const ulonglong2*>(wr + m * 4);
                #pragma unroll
                for (int r = 0; r < R; r++) {
                    ffma2(acc[r][2 * m],     f0[r], w.x);
                    ffma2(acc[r][2 * m + 1], f0[r], w.y);
                }
            }
            {
                ull w12 = *reinterpret_cast<const ull*>(wr + 24);
                #pragma unroll
                for (int r = 0; r < R; r++) ffma2(acc[r][12], f0[r], w12);
            }
            // k1
            #pragma unroll
            for (int m = 0; m < 6; m++) {
                ulonglong2 w = *reinterpret_cast<const ulonglong2*>(wr + WROW + m * 4);
                #pragma unroll
                for (int r = 0; r < R; r++) {
                    ffma2(acc[r][2 * m],     f1[r], w.x);
                    ffma2(acc[r][2 * m + 1], f1[r], w.y);
                }
            }
            {
                ull w12 = *reinterpret_cast<const ull*>(wr + WROW + 24);
                #pragma unroll
                for (int r = 0; r < R; r++) ffma2(acc[r][12], f1[r], w12);
            }
        }
    }
    __syncthreads();

    // ---- unpack u_hat ----
    float u[R][26];
    #pragma unroll
    for (int r = 0; r < R; r++)
        #pragma unroll
        for (int p = 0; p < NPAIR; p++)
            unpack2(acc[r][p], u[r][2 * p], u[r][2 * p + 1]);

    float bb[R][5];
    #pragma unroll
    for (int r = 0; r < R; r++)
        #pragma unroll
        for (int i = 0; i < 5; i++) bb[r][i] = 0.f;

    const int lane = t & 31, g = t >> 5;

    // ---- 4 routing iterations ----
    for (int it = 0; it < 4; it++) {
        float cw[R][5];
        #pragma unroll
        for (int r = 0; r < R; r++) {
            float m = bb[r][0];
            #pragma unroll
            for (int i = 1; i < 5; i++) m = fmaxf(m, bb[r][i]);
            float e[5], s = 0.f;
            #pragma unroll
            for (int i = 0; i < 5; i++) { e[i] = __expf(bb[r][i] - m); s += e[i]; }
            float inv = 1.f / s;
            #pragma unroll
            for (int i = 0; i < 5; i++) cw[r][i] = e[i] * inv;
        }
        #pragma unroll
        for (int c = 0; c < 25; c++) {
            float s = 0.f;
            #pragma unroll
            for (int r = 0; r < R; r++) s += cw[r][c / 5] * u[r][c];
            scratch[t * SCR_STRIDE + c] = s;
        }
        __syncthreads();
        if (lane < 25) {
            float s = 0.f;
            #pragma unroll
            for (int uu = 0; uu < 32; uu++) s += scratch[(g * 32 + uu) * SCR_STRIDE + lane];
            red[g * 26 + lane] = s;
        }
        __syncthreads();
        if (t < 25) {
            float s = 0.f;
            #pragma unroll
            for (int gg = 0; gg < 4; gg++) s += red[gg * 26 + t];
            raw[t] = s;
        }
        __syncthreads();
        if (t < 25) {
            int i5 = (t / 5) * 5;
            float sq = 0.f;
            #pragma unroll
            for (int k = 0; k < 5; k++) { float v = raw[i5 + k]; sq += v * v; }
            sOut[t] = raw[t] * rsqrtf(sq + 1e-7f);   // squash = pure norm-normalization
        }
        __syncthreads();
        if (it < 3) {
            float ov[25];
            #pragma unroll
            for (int c = 0; c < 25; c++) ov[c] = sOut[c];
            #pragma unroll
            for (int r = 0; r < R; r++)
                #pragma unroll
                for (int i = 0; i < 5; i++) {
                    float s = 0.f;
                    #pragma unroll
                    for (int k = 0; k < 5; k++) s += ov[i * 5 + k] * u[r][i * 5 + k];
                    bb[r][i] = s;   // b REPLACED each iteration (matches reference)
                }
        }
    }

    if (t < 25) out[b * 25 + t] = sOut[t];
}

extern "C" void kernel_launch(void* const* d_in, const int* in_sizes, int n_in,
                              void* d_out, int out_size)
{
    const float* x = (const float*)d_in[0];
    const float* W = (const float*)d_in[1];
    float* out = (float*)d_out;
    cudaFuncSetAttribute(caps_kernel, cudaFuncAttributeMaxDynamicSharedMemorySize, SMEM_BYTES);
    caps_kernel<<<1024, THREADS, SMEM_BYTES>>>(x, W, out);
}

// round 6
// speedup vs baseline: 1.0676x; 1.0676x over previous
#include <cuda_runtime.h>
#include <cstdint>

#define THREADS 256
#define KDIM 120
#define INP 512
#define KC 24
#define NCHUNK 5
#define NJ2 12            // k-pairs per chunk
#define A_STRIDE 516      // plane row stride in floats (R3-proven, conflict-free)
#define WROW 32           // W k-row padded to 32 floats; group0 @ +0, group1 @ +16

// float offsets in dynamic smem
#define U_OFF (KDIM * WROW)                      // 3840
#define PLANE_FLOATS (NJ2 * A_STRIDE)            // 6192
#define SCR_OFF U_OFF                            // routing scratch aliases planes
#define SCR_STRIDE 15
#define PEX_OFF (U_OFF + THREADS * SCR_STRIDE)   // 7680 (< plane end 16224)
#define PEX_STRIDE 21
#define RED_OFF (U_OFF + 2 * PLANE_FLOATS)       // 16224
#define RAW_OFF (RED_OFF + 8 * 16)               // 16352
#define SOUT_OFF (RAW_OFF + 32)
#define SMEM_FLOATS (SOUT_OFF + 32)              // 16416
#define SMEM_BYTES (SMEM_FLOATS * 4)             // 65664

typedef unsigned long long ull;

__device__ __forceinline__ ull dup2(float v) {
    ull r;
    asm("mov.b64 %0, {%1, %1};" : "=l"(r) : "r"(__float_as_uint(v)));
    return r;
}
__device__ __forceinline__ void ffma2(ull& d, ull a, ull b) {
    asm("fma.rn.f32x2 %0, %1, %2, %0;" : "+l"(d) : "l"(a), "l"(b));
}
__device__ __forceinline__ void unpack2(ull v, float& lo, float& hi) {
    unsigned int a, b2;
    asm("mov.b64 {%0, %1}, %2;" : "=r"(a), "=r"(b2) : "l"(v));
    lo = __uint_as_float(a);
    hi = __uint_as_float(b2);
}

extern __shared__ float smem[];

__global__ void __launch_bounds__(THREADS, 2)
caps_kernel(const float* __restrict__ x, const float* __restrict__ W, float* __restrict__ out)
{
    const int b    = blockIdx.x;
    const int t    = threadIdx.x;
    const int rt   = t & 127;      // row-thread: owns rows 4rt..4rt+3
    const int cg   = t >> 7;       // column group: pairs cg*7 .. cg*7+6
    const int lane = t & 31;
    const int wid  = t >> 5;

    float* sW      = smem;                          // [120][32]
    float* sXA     = smem + U_OFF;                  // plane A: rows (4i,4i+1)
    float* sXB     = smem + U_OFF + PLANE_FLOATS;   // plane B: rows (4i+2,4i+3)
    float* scratch = smem + SCR_OFF;                // [256][15] (aliases planes)
    float* pexch   = smem + PEX_OFF;                // [256][21] (aliases planes)
    float* red     = smem + RED_OFF;                // [8][16]
    float* raw     = smem + RAW_OFF;                // [25]
    float* sOut    = smem + SOUT_OFF;               // [25]

    // ---- stage W: k-row padded to 32; floats 0-13 = cols 0-13, floats 16-29 = cols 14-27 ----
    for (int idx = t; idx < KDIM * WROW; idx += THREADS) {
        int j = idx >> 5, f = idx & 31;
        int col = (f < 14) ? f : ((f >= 16 && f < 30) ? (f - 2) : -1);
        smem[idx] = (col >= 0 && col < 25) ? W[j * 25 + col] : 0.f;
    }

    // ---- GEMM: u_hat[4 rows][14 cols(my half)] in 28 f32x2 accumulators ----
    ull acc[4][7];
    #pragma unroll
    for (int r = 0; r < 4; r++)
        #pragma unroll
        for (int p = 0; p < 7; p++) acc[r][p] = 0ull;

    const float4* xg = reinterpret_cast<const float4*>(x) + (size_t)b * (INP * KDIM / 4);

    for (int kc = 0; kc < NCHUNK; kc++) {
        __syncthreads();                 // planes safe to overwrite (covers sW on first pass)
        const int k0q = kc * (KC / 4);
        #pragma unroll
        for (int it2 = 0; it2 < (INP * (KC / 4)) / THREADS; it2++) {   // 12 float4/thread
            int idx  = t + it2 * THREADS;
            int row  = idx / (KC / 4);
            int slot = idx % (KC / 4);
            float4 v = xg[row * (KDIM / 4) + k0q + slot];
            // plane by (row mod 4): {0,1}->A, {2,3}->B; within plane: rp=row>>2, parity=row&1
            float* plane = ((row >> 1) & 1) ? sXB : sXA;
            float* p0 = plane + (2 * slot) * A_STRIDE + (row >> 2) * 4 + (row & 1) * 2;
            *reinterpret_cast<float2*>(p0)            = make_float2(v.x, v.y);  // j2 = 2*slot
            *reinterpret_cast<float2*>(p0 + A_STRIDE) = make_float2(v.z, v.w);  // j2 = 2*slot+1
        }
        __syncthreads();

        #pragma unroll 2
        for (int j2 = 0; j2 < NJ2; j2++) {
            float4 xa = *reinterpret_cast<const float4*>(sXA + j2 * A_STRIDE + rt * 4);
            float4 xb = *reinterpret_cast<const float4*>(sXB + j2 * A_STRIDE + rt * 4);
            ull f0[4] = { dup2(xa.x), dup2(xa.z), dup2(xb.x), dup2(xb.z) };  // k0
            ull f1[4] = { dup2(xa.y), dup2(xa.w), dup2(xb.y), dup2(xb.w) };  // k1

            const float* wr0 = sW + (kc * KC + 2 * j2) * WROW + cg * 16;
            // k0
            {
                ulonglong2 w01 = *reinterpret_cast<const ulonglong2*>(wr0);
                ulonglong2 w23 = *reinterpret_cast<const ulonglong2*>(wr0 + 4);
                ulonglong2 w45 = *reinterpret_cast<const ulonglong2*>(wr0 + 8);
                ull        w6  = *reinterpret_cast<const ull*>(wr0 + 12);
                #pragma unroll
                for (int r = 0; r < 4; r++) {
                    ffma2(acc[r][0], f0[r], w01.x);
                    ffma2(acc[r][1], f0[r], w01.y);
                    ffma2(acc[r][2], f0[r], w23.x);
                    ffma2(acc[r][3], f0[r], w23.y);
                    ffma2(acc[r][4], f0[r], w45.x);
                    ffma2(acc[r][5], f0[r], w45.y);
                    ffma2(acc[r][6], f0[r], w6);
                }
            }
            // k1
            {
                const float* wr1 = wr0 + WROW;
                ulonglong2 w01 = *reinterpret_cast<const ulonglong2*>(wr1);
                ulonglong2 w23 = *reinterpret_cast<const ulonglong2*>(wr1 + 4);
                ulonglong2 w45 = *reinterpret_cast<const ulonglong2*>(wr1 + 8);
                ull        w6  = *reinterpret_cast<const ull*>(wr1 + 12);
                #pragma unroll
                for (int r = 0; r < 4; r++) {
                    ffma2(acc[r][0], f1[r], w01.x);
                    ffma2(acc[r][1], f1[r], w01.y);
                    ffma2(acc[r][2], f1[r], w23.x);
                    ffma2(acc[r][3], f1[r], w23.y);
                    ffma2(acc[r][4], f1[r], w45.x);
                    ffma2(acc[r][5], f1[r], w45.y);
                    ffma2(acc[r][6], f1[r], w6);
                }
            }
        }
    }
    __syncthreads();

    // ---- unpack u_hat (my half: local cols 0..13 = global cg*14 .. cg*14+13) ----
    float u[4][14];
    #pragma unroll
    for (int r = 0; r < 4; r++)
        #pragma unroll
        for (int p = 0; p < 7; p++)
            unpack2(acc[r][p], u[r][2 * p], u[r][2 * p + 1]);

    float bb[4][5];
    #pragma unroll
    for (int r = 0; r < 4; r++)
        #pragma unroll
        for (int i = 0; i < 5; i++) bb[r][i] = 0.f;

    const int gbase = cg * 14;

    // ---- 4 routing iterations ----
    for (int it = 0; it < 4; it++) {
        // softmax over capsules per owned row
        float cw[4][5];
        #pragma unroll
        for (int r = 0; r < 4; r++) {
            float m = bb[r][0];
            #pragma unroll
            for (int i = 1; i < 5; i++) m = fmaxf(m, bb[r][i]);
            float e[5], s = 0.f;
            #pragma unroll
            for (int i = 0; i < 5; i++) { e[i] = __expf(bb[r][i] - m); s += e[i]; }
            float inv = 1.f / s;
            #pragma unroll
            for (int i = 0; i < 5; i++) cw[r][i] = e[i] * inv;
        }
        // per-thread partials for my 14 local cols
        #pragma unroll
        for (int c = 0; c < 14; c++) {
            int g = gbase + c;
            float s = 0.f;
            if (g < 25) {
                int cap = g / 5;
                #pragma unroll
                for (int r = 0; r < 4; r++) s += cw[r][cap] * u[r][c];
            }
            scratch[t * SCR_STRIDE + c] = s;
        }
        __syncthreads();
        // warp reduce (each warp sums its 32 threads per local col)
        if (lane < 14) {
            float s = 0.f;
            #pragma unroll
            for (int uu = 0; uu < 32; uu++) s += scratch[(wid * 32 + uu) * SCR_STRIDE + lane];
            red[wid * 16 + lane] = s;
        }
        __syncthreads();
        if (t < 25) {
            int cgp = (t >= 14) ? 1 : 0;
            int loc = t - cgp * 14;
            float s = 0.f;
            #pragma unroll
            for (int ww = 0; ww < 4; ww++) s += red[(cgp * 4 + ww) * 16 + loc];
            raw[t] = s;
        }
        __syncthreads();
        if (t < 25) {
            int i5 = (t / 5) * 5;
            float sq = 0.f;
            #pragma unroll
            for (int k = 0; k < 5; k++) { float v = raw[i5 + k]; sq += v * v; }
            sOut[t] = raw[t] * rsqrtf(sq + 1e-7f);   // squash = pure norm-normalization
        }
        __syncthreads();
        if (it < 3) {
            // partial b-update over my cols, then exchange halves with partner t^128
            float pb[4][5];
            #pragma unroll
            for (int r = 0; r < 4; r++)
                #pragma unroll
                for (int i = 0; i < 5; i++) pb[r][i] = 0.f;
            #pragma unroll
            for (int c = 0; c < 14; c++) {
                int g = gbase + c;
                if (g < 25) {
                    int cap = g / 5;
                    float ov = sOut[g];
                    #pragma unroll
                    for (int r = 0; r < 4; r++) pb[r][cap] += ov * u[r][c];
                }
            }
            #pragma unroll
            for (int r = 0; r < 4; r++)
                #pragma unroll
                for (int i = 0; i < 5; i++)
                    pexch[t * PEX_STRIDE + r * 5 + i] = pb[r][i];
            __syncthreads();
            int prt = t ^ 128;
            #pragma unroll
            for (int r = 0; r < 4; r++)
                #pragma unroll
                for (int i = 0; i < 5; i++)
                    bb[r][i] = pb[r][i] + pexch[prt * PEX_STRIDE + r * 5 + i];  // b REPLACED
            __syncthreads();
        }
    }

    if (t < 25) out[b * 25 + t] = sOut[t];
}

extern "C" void kernel_launch(void* const* d_in, const int* in_sizes, int n_in,
                              void* d_out, int out_size)
{
    const float* x = (const float*)d_in[0];
    const float* W = (const float*)d_in[1];
    float* out = (float*)d_out;
    cudaFuncSetAttribute(caps_kernel, cudaFuncAttributeMaxDynamicSharedMemorySize, SMEM_BYTES);
    caps_kernel<<<1024, THREADS, SMEM_BYTES>>>(x, W, out);
}

// round 7
// speedup vs baseline: 1.5218x; 1.4254x over previous
#include <cuda_runtime.h>
#include <cstdint>

#define THREADS 256
#define KDIM 120
#define INP 512
#define NPAIR 13
#define KC 24
#define NCHUNK 5
#define NJ2 12
#define X_STRIDE 1028     // proven layout from the 117us kernel

// dynamic smem float offsets (W no longer staged in SMEM)
#define SX_FLOATS (NJ2 * X_STRIDE)           // 12336
#define SCR_STRIDE 27                        // scratch aliases sX (256*27=6912 < 12336)
#define RED_OFF SX_FLOATS                    // [8][26]
#define RAW_OFF (RED_OFF + 8 * 26)
#define OUT_OFF (RAW_OFF + 32)
#define SMEM_FLOATS (OUT_OFF + 32)           // 12608
#define SMEM_BYTES (SMEM_FLOATS * 4)         // 50432

typedef unsigned long long ull;

// W packed [120][26] floats (col 25 = 0): viewed as 780 ulonglong2.
// j2-block g (k0=2g, k1=2g+1) = cW2[g*13 .. g*13+12]:
//   ull index 0..12  -> k0 col-pairs 0..12
//   ull index 13..25 -> k1 col-pairs 0..12
__constant__ ulonglong2 cW2[780];   // zero-initialized; pad lanes never written

__device__ __forceinline__ ull dup2(float v) {
    ull r;
    asm("mov.b64 %0, {%1, %1};" : "=l"(r) : "r"(__float_as_uint(v)));
    return r;
}
__device__ __forceinline__ void ffma2(ull& d, ull a, ull b) {
    asm("fma.rn.f32x2 %0, %1, %2, %0;" : "+l"(d) : "l"(a), "l"(b));
}
__device__ __forceinline__ void unpack2(ull v, float& lo, float& hi) {
    unsigned int a, b2;
    asm("mov.b64 {%0, %1}, %2;" : "=r"(a), "=r"(b2) : "l"(v));
    lo = __uint_as_float(a);
    hi = __uint_as_float(b2);
}

extern __shared__ float smem[];

__global__ void __launch_bounds__(THREADS, 2)
caps_kernel(const float* __restrict__ x, float* __restrict__ out)
{
    const int b = blockIdx.x;
    const int t = threadIdx.x;
    const int lane = t & 31, g = t >> 5;

    float* sX      = smem;                 // [NJ2][X_STRIDE]
    float* scratch = smem;                 // routing partials alias sX
    float* red     = smem + RED_OFF;       // [8][26]
    float* raw     = smem + RAW_OFF;       // [25]
    float* sOut    = smem + OUT_OFF;       // [25]

    // ---- GEMM: u_hat[2 rows][26 cols] in 26 f32x2 accumulators, W from constant ----
    ull acc[2][NPAIR];
    #pragma unroll
    for (int r = 0; r < 2; r++)
        #pragma unroll
        for (int p = 0; p < NPAIR; p++) acc[r][p] = 0ull;

    const float4* xg = reinterpret_cast<const float4*>(x) + (size_t)b * (INP * KDIM / 4);

    for (int kc = 0; kc < NCHUNK; kc++) {
        __syncthreads();                 // sX safe to overwrite
        const int k0q = kc * (KC / 4);
        #pragma unroll
        for (int it2 = 0; it2 < (INP * (KC / 4)) / THREADS; it2++) {   // 12 float4/thread
            int idx  = t + it2 * THREADS;
            int row  = idx / (KC / 4);
            int slot = idx % (KC / 4);
            float4 v = xg[row * (KDIM / 4) + k0q + slot];
            float* p0 = sX + (2 * slot) * X_STRIDE + (row >> 1) * 4 + (row & 1) * 2;
            *reinterpret_cast<float2*>(p0)            = make_float2(v.x, v.y);  // j2 = 2*slot
            *reinterpret_cast<float2*>(p0 + X_STRIDE) = make_float2(v.z, v.w);  // j2 = 2*slot+1
        }
        __syncthreads();

        const ulonglong2* wb = cW2 + kc * NJ2 * NPAIR;
        #pragma unroll
        for (int j2 = 0; j2 < NJ2; j2++) {
            // {x(k0,r0), x(k1,r0), x(k0,r1), x(k1,r1)}
            float4 xv = *reinterpret_cast<const float4*>(sX + j2 * X_STRIDE + t * 4);
            ull a0 = dup2(xv.x);   // k0, row0
            ull a1 = dup2(xv.y);   // k1, row0
            ull b0 = dup2(xv.z);   // k0, row1
            ull b1 = dup2(xv.w);   // k1, row1

            const ulonglong2* wq = wb + j2 * NPAIR;
            // q = 0..5 : k0 pairs (2q, 2q+1)
            #pragma unroll
            for (int q = 0; q < 6; q++) {
                ulonglong2 v = wq[q];
                ffma2(acc[0][2 * q],     a0, v.x);
                ffma2(acc[1][2 * q],     b0, v.x);
                ffma2(acc[0][2 * q + 1], a0, v.y);
                ffma2(acc[1][2 * q + 1], b0, v.y);
            }
            // q = 6 : k0 pair 12, k1 pair 0
            {
                ulonglong2 v = wq[6];
                ffma2(acc[0][12], a0, v.x);
                ffma2(acc[1][12], b0, v.x);
                ffma2(acc[0][0],  a1, v.y);
                ffma2(acc[1][0],  b1, v.y);
            }
            // q = 7..12 : k1 pairs (2q-13, 2q-12)
            #pragma unroll
            for (int q = 7; q < 13; q++) {
                ulonglong2 v = wq[q];
                ffma2(acc[0][2 * q - 13], a1, v.x);
                ffma2(acc[1][2 * q - 13], b1, v.x);
                ffma2(acc[0][2 * q - 12], a1, v.y);
                ffma2(acc[1][2 * q - 12], b1, v.y);
            }
        }
    }
    __syncthreads();

    // ---- unpack u_hat ----
    float u[2][26];
    #pragma unroll
    for (int r = 0; r < 2; r++)
        #pragma unroll
        for (int p = 0; p < NPAIR; p++)
            unpack2(acc[r][p], u[r][2 * p], u[r][2 * p + 1]);

    float bb[2][5];
    #pragma unroll
    for (int r = 0; r < 2; r++)
        #pragma unroll
        for (int i = 0; i < 5; i++) bb[r][i] = 0.f;

    // ---- 4 routing iterations (verbatim from the 117us kernel) ----
    for (int it = 0; it < 4; it++) {
        float cw[2][5];
        #pragma unroll
        for (int r = 0; r < 2; r++) {
            float m = bb[r][0];
            #pragma unroll
            for (int i = 1; i < 5; i++) m = fmaxf(m, bb[r][i]);
            float e[5], s = 0.f;
            #pragma unroll
            for (int i = 0; i < 5; i++) { e[i] = __expf(bb[r][i] - m); s += e[i]; }
            float inv = 1.f / s;
            #pragma unroll
            for (int i = 0; i < 5; i++) cw[r][i] = e[i] * inv;
        }
        #pragma unroll
        for (int c = 0; c < 25; c++)
            scratch[t * SCR_STRIDE + c] = cw[0][c / 5] * u[0][c] + cw[1][c / 5] * u[1][c];
        __syncthreads();
        if (lane < 25) {
            float s = 0.f;
            #pragma unroll
            for (int uu = 0; uu < 32; uu++) s += scratch[(g * 32 + uu) * SCR_STRIDE + lane];
            red[g * 26 + lane] = s;
        }
        __syncthreads();
        if (t < 25) {
            float s = 0.f;
            #pragma unroll
            for (int gg = 0; gg < 8; gg++) s += red[gg * 26 + t];
            raw[t] = s;
        }
        __syncthreads();
        if (t < 25) {
            int i5 = (t / 5) * 5;
            float sq = 0.f;
            #pragma unroll
            for (int k = 0; k < 5; k++) { float v = raw[i5 + k]; sq += v * v; }
            sOut[t] = raw[t] * rsqrtf(sq + 1e-7f);   // squash = pure norm-normalization
        }
        __syncthreads();
        if (it < 3) {
            float ov[25];
            #pragma unroll
            for (int c = 0; c < 25; c++) ov[c] = sOut[c];
            #pragma unroll
            for (int r = 0; r < 2; r++)
                #pragma unroll
                for (int i = 0; i < 5; i++) {
                    float s = 0.f;
                    #pragma unroll
                    for (int k = 0; k < 5; k++) s += ov[i * 5 + k] * u[r][i * 5 + k];
                    bb[r][i] = s;   // b REPLACED each iteration (matches reference)
                }
        }
    }

    if (t < 25) out[b * 25 + t] = sOut[t];
}

extern "C" void kernel_launch(void* const* d_in, const int* in_sizes, int n_in,
                              void* d_out, int out_size)
{
    const float* x = (const float*)d_in[0];
    const float* W = (const float*)d_in[1];
    float* out = (float*)d_out;

    // Pack W[120][25] -> constant [120][26] floats (col 25 stays 0 from static init).
    // Strided D2D async memcpy: dst pitch 104B, src pitch 100B, width 100B, 120 rows.
    void* csym = nullptr;
    cudaGetSymbolAddress(&csym, cW2);
    cudaMemcpy2DAsync(csym, 26 * sizeof(float),
                      W, 25 * sizeof(float),
                      25 * sizeof(float), KDIM,
                      cudaMemcpyDeviceToDevice, 0);

    cudaFuncSetAttribute(caps_kernel, cudaFuncAttributeMaxDynamicSharedMemorySize, SMEM_BYTES);
    caps_kernel<<<1024, THREADS, SMEM_BYTES>>>(x, out);
}